// round 1
// baseline (speedup 1.0000x reference)
#include <cuda_runtime.h>
#include <stdint.h>

// BFP quantizer: x (64, 256, 56, 56) fp32 NCHW, tile=8 along C (axis 1).
// bitwidth=16 -> m=7 mantissa bits, qmax=127, step=2^(shared_exp-6).
// shared_exp = floor(log2(max(|x| over tile), eps)), eps=2^-23.
//
// Decomposition: thread = (n, c_tile, hw4). Loads 8 float4 (one per channel
// in the tile, stride HW floats), computes 4 independent per-lane maxes,
// quantizes, writes 8 float4. All accesses 16B-vectorized and coalesced.

#define N_DIM   64
#define C_DIM   256
#define HW_DIM  3136            // 56*56
#define TILE_C  8
#define NTILES  (C_DIM / TILE_C)   // 32
#define HW4     (HW_DIM / 4)       // 784
#define EPS_F   1.1920928955078125e-07f  // 2^-23

__global__ __launch_bounds__(256)
void bfp_quant_kernel(const float4* __restrict__ in, float4* __restrict__ out)
{
    int t = blockIdx.x * blockDim.x + threadIdx.x;
    // t in [0, N*NTILES*HW4)
    int w4   = t % HW4;
    int rest = t / HW4;
    int ct   = rest % NTILES;
    int n    = rest / NTILES;

    // base index in float4 units
    long base = (long)n * (C_DIM * HW4) + (long)ct * (TILE_C * HW4) + w4;

    // Load 8 float4 (front-batched for MLP)
    float a[TILE_C][4];
    #pragma unroll
    for (int k = 0; k < TILE_C; k++) {
        float4 v = in[base + (long)k * HW4];
        a[k][0] = v.x; a[k][1] = v.y; a[k][2] = v.z; a[k][3] = v.w;
    }

    #pragma unroll
    for (int j = 0; j < 4; j++) {
        // tile max(|x|), clamped by eps
        float mx = EPS_F;
        #pragma unroll
        for (int k = 0; k < TILE_C; k++)
            mx = fmaxf(mx, fabsf(a[k][j]));

        // shared_exp = floor(log2(mx)) via exponent bits (mx is normal, positive)
        int e = (int)(__float_as_uint(mx) >> 23) - 127;

        // inv_step = 2^(6 - e), step = 2^(e - 6)
        float inv_step = __uint_as_float((uint32_t)(133 - e) << 23);
        float step     = __uint_as_float((uint32_t)(e + 121) << 23);

        #pragma unroll
        for (int k = 0; k < TILE_C; k++) {
            float q = rintf(a[k][j] * inv_step);      // round-half-to-even
            q = fminf(fmaxf(q, -127.0f), 127.0f);     // clamp to +/-(2^7 - 1)
            a[k][j] = q * step;
        }
    }

    #pragma unroll
    for (int k = 0; k < TILE_C; k++) {
        float4 v;
        v.x = a[k][0]; v.y = a[k][1]; v.z = a[k][2]; v.w = a[k][3];
        out[base + (long)k * HW4] = v;
    }
}

extern "C" void kernel_launch(void* const* d_in, const int* in_sizes, int n_in,
                              void* d_out, int out_size)
{
    const float4* in  = (const float4*)d_in[0];
    float4*       out = (float4*)d_out;

    const int total_threads = N_DIM * NTILES * HW4;   // 1,605,632
    const int block = 256;
    const int grid  = total_threads / block;          // 6272 exactly

    bfp_quant_kernel<<<grid, block>>>(in, out);
}